// round 1
// baseline (speedup 1.0000x reference)
#include <cuda_runtime.h>
#include <cuda_bf16.h>
#include <math.h>

// ---------------------------------------------------------------------------
// DeepDCNN: emb-gather -> 4x [grouped conv -> fold -> ordered top-k -> tanh] -> FC
// Shapes: B=64, SEQ=1024, E=64, V=50000, NC=6
// Layer i: groups G=[64,32,16,8], Cin/group=[1,10,14,18], NF=[10,14,18,22],
//          KS=[7,5,5,3], conv out len = Sin+KS-1, fold halves group count,
//          kpool=[768,512,256,4]
// ---------------------------------------------------------------------------

// Scratch buffers (ping-pong). Sizes in floats.
__device__ float g_bufA[21094400]; // max conv-out (layer0: 64*320*1030)
__device__ float g_bufB[15728640]; // max pooled   (layer0: 64*320*768)
__device__ float g_bufC[7340032];  // embed (4.19M) / pooled layer1 (7.34M)

// ---------------------------------------------------------------------------
// 1) Embedding gather + transpose: X[b][e][s] = emb[tokens[b][s]][e]
// ---------------------------------------------------------------------------
__global__ void embed_kernel(const int* __restrict__ tokens,
                             const float* __restrict__ emb,
                             float* __restrict__ X)
{
    int idx = blockIdx.x * 256 + threadIdx.x;   // flattened (b, s), B*SEQ = 65536
    int b = idx >> 10;
    int s = idx & 1023;
    int tok = tokens[idx];
    const float* er = emb + (long long)tok * 64;
    float* xr = X + (long long)b * 64 * 1024 + s;
    #pragma unroll 8
    for (int e = 0; e < 64; ++e)
        xr[(long long)e * 1024] = er[e];
}

// ---------------------------------------------------------------------------
// 2) Fused grouped conv + bias + fold.
// Output: y[b][gp*NF+f][s] = sum_{p in 0,1} ( b[(2gp+p)*NF+f] +
//     sum_{c,j} w[(2gp+p)*NF+f][c][j] * x[b][(2gp+p)*CING+c][s+j-(KS-1)] )
// s in [0, SOUT), SOUT = SIN + KS - 1, zero padding outside [0,SIN).
// Block: 128 threads; each thread computes 2 s-positions; tile TS=256.
// ---------------------------------------------------------------------------
template<int CING, int NF, int KS>
__global__ __launch_bounds__(128)
void conv_fold_kernel(const float* __restrict__ x, const float* __restrict__ w,
                      const float* __restrict__ bias, float* __restrict__ y,
                      int SIN, int SOUT, int Ghalf, int stiles)
{
    constexpr int TS = 256;
    constexpr int LX = TS + KS - 1;
    __shared__ float sw[2 * NF * CING * KS];
    __shared__ float sx[2 * CING * LX];

    int bid  = blockIdx.x;
    int tile = bid % stiles;
    int gp   = (bid / stiles) % Ghalf;
    int b    = bid / (stiles * Ghalf);
    int t    = threadIdx.x;
    int s0   = tile * TS;

    const int CH_IN  = Ghalf * 2 * CING;
    const int CH_OUT = Ghalf * NF;

    // weights for the two paired groups, contiguous in global memory
    for (int e = t; e < 2 * NF * CING * KS; e += 128) {
        // global layout: w[(g*NF + f)*CING*KS + c*KS + j], g = 2*gp + e/(NF*CING*KS)
        sw[e] = w[(long long)(2 * gp) * NF * CING * KS + e];
    }
    // input tile with halo + zero padding
    const float* xb = x + (long long)b * CH_IN * SIN;
    for (int e = t; e < 2 * CING * LX; e += 128) {
        int pc = e / LX;          // p*CING + c
        int i  = e % LX;
        int gs = s0 - (KS - 1) + i;
        float v = 0.f;
        if (gs >= 0 && gs < SIN)
            v = xb[(long long)(2 * gp * CING + pc) * SIN + gs];
        sx[e] = v;
    }
    __syncthreads();

    float acc0[NF], acc1[NF];
    #pragma unroll
    for (int f = 0; f < NF; ++f) {
        float bb = bias[(2 * gp) * NF + f] + bias[(2 * gp + 1) * NF + f];
        acc0[f] = bb;
        acc1[f] = bb;
    }

    for (int p = 0; p < 2; ++p) {
        for (int c = 0; c < CING; ++c) {
            const float* sxr = &sx[(p * CING + c) * LX];
            const float* swr = &sw[p * NF * CING * KS + c * KS];
            #pragma unroll
            for (int j = 0; j < KS; ++j) {
                float x0 = sxr[t + j];
                float x1 = sxr[t + 128 + j];
                #pragma unroll
                for (int f = 0; f < NF; ++f) {
                    float wv = swr[f * CING * KS + j];
                    acc0[f] = fmaf(wv, x0, acc0[f]);
                    acc1[f] = fmaf(wv, x1, acc1[f]);
                }
            }
        }
    }

    float* yb = y + (long long)b * CH_OUT * SOUT + (long long)gp * NF * SOUT;
    int s_a = s0 + t, s_b = s0 + t + 128;
    #pragma unroll
    for (int f = 0; f < NF; ++f) {
        if (s_a < SOUT) yb[(long long)f * SOUT + s_a] = acc0[f];
        if (s_b < SOUT) yb[(long long)f * SOUT + s_b] = acc1[f];
    }
}

// ---------------------------------------------------------------------------
// 3) Ordered top-k + tanh per row. One block (256 thr) per (b, channel) row.
// Radix-select (4 x 8-bit, MSB first) over monotone-flipped float keys
// finds the k-th largest key T; stable compaction keeps all keys > T plus the
// first (k - count_gt) keys == T in original index order (matches lax.top_k
// tie-breaking), applies tanh, writes densely.
// ---------------------------------------------------------------------------
__global__ __launch_bounds__(256)
void kmax_tanh_kernel(const float* __restrict__ x, float* __restrict__ y,
                      int n, int k)
{
    __shared__ unsigned skey[1032];
    __shared__ int hist[256];
    __shared__ unsigned wscan[8];
    __shared__ unsigned sh_dig, sh_krem, sh_tot;

    int row = blockIdx.x;
    int t   = threadIdx.x;
    const float* xr = x + (long long)row * n;

    for (int i = t; i < n; i += 256) {
        unsigned u = __float_as_uint(xr[i]);
        skey[i] = (u & 0x80000000u) ? ~u : (u | 0x80000000u);
    }
    __syncthreads();

    unsigned prefix = 0;
    int krem = k;
    for (int shift = 24; shift >= 0; shift -= 8) {
        hist[t] = 0;
        __syncthreads();
        unsigned hm = (shift == 24) ? 0u : (0xFFFFFFFFu << (shift + 8));
        for (int i = t; i < n; i += 256) {
            unsigned key = skey[i];
            if ((key & hm) == prefix)
                atomicAdd(&hist[(key >> shift) & 255], 1);
        }
        __syncthreads();
        if (t == 0) {
            int cum = 0, d = 0;
            for (int bb = 255; bb >= 0; --bb) {
                int c = hist[bb];
                if (cum + c >= krem) { d = bb; break; }
                cum += c;
            }
            sh_dig  = (unsigned)d;
            sh_krem = (unsigned)(krem - cum);
        }
        __syncthreads();
        prefix |= (sh_dig << shift);
        krem = (int)sh_krem;
        __syncthreads();
    }
    const unsigned T = prefix;
    const int need_eq = krem;   // equals to keep (lowest indices first)

    int lane = t & 31, wid = t >> 5;
    int carry_gt = 0, carry_eq = 0;
    for (int base = 0; base < n; base += 256) {
        int i = base + t;
        unsigned key = 0;
        int gt = 0, eq = 0;
        if (i < n) { key = skey[i]; gt = key > T; eq = key == T; }
        unsigned pk = ((unsigned)gt << 16) | (unsigned)eq;
        unsigned v = pk;
        #pragma unroll
        for (int off = 1; off < 32; off <<= 1) {
            unsigned u = __shfl_up_sync(0xFFFFFFFFu, v, off);
            if (lane >= off) v += u;
        }
        if (lane == 31) wscan[wid] = v;
        __syncthreads();
        if (t < 8) {
            unsigned wv = wscan[t];
            unsigned vv = wv;
            #pragma unroll
            for (int off = 1; off < 8; off <<= 1) {
                unsigned u = __shfl_up_sync(0xFFu, vv, off);
                if (t >= off) vv += u;
            }
            wscan[t] = vv - wv;           // exclusive warp prefix
            if (t == 7) sh_tot = vv;       // block total (packed)
        }
        __syncthreads();
        unsigned excl = v - pk + wscan[wid];
        int ggt = carry_gt + (int)(excl >> 16);
        int geq = carry_eq + (int)(excl & 0xFFFFu);
        if (i < n && (gt || (eq && geq < need_eq))) {
            int pos = ggt + min(geq, need_eq);
            float f = (key & 0x80000000u) ? __uint_as_float(key & 0x7FFFFFFFu)
                                          : __uint_as_float(~key);
            y[(long long)row * k + pos] = tanhf(f);
        }
        carry_gt += (int)(sh_tot >> 16);
        carry_eq += (int)(sh_tot & 0xFFFFu);
        __syncthreads();
    }
}

// ---------------------------------------------------------------------------
// 4) Final FC: out[b][n] = fcb[n] + sum_i x[b][i] * fcw[n][i],  i < 352
// ---------------------------------------------------------------------------
__global__ void fc_kernel(const float* __restrict__ x, const float* __restrict__ fcw,
                          const float* __restrict__ fcb, float* __restrict__ out)
{
    int t = blockIdx.x * blockDim.x + threadIdx.x;
    if (t >= 64 * 6) return;
    int b = t / 6, n = t % 6;
    const float* xr = x + b * 352;
    const float* wr = fcw + n * 352;
    float acc = fcb[n];
    #pragma unroll 4
    for (int i = 0; i < 352; ++i) acc = fmaf(xr[i], wr[i], acc);
    out[t] = acc;
}

// ---------------------------------------------------------------------------
extern "C" void kernel_launch(void* const* d_in, const int* in_sizes, int n_in,
                              void* d_out, int out_size)
{
    (void)in_sizes; (void)n_in; (void)out_size;
    const int*   tokens = (const int*)  d_in[0];
    const float* emb    = (const float*)d_in[1];
    const float* w1 = (const float*)d_in[2];
    const float* b1 = (const float*)d_in[3];
    const float* w2 = (const float*)d_in[4];
    const float* b2 = (const float*)d_in[5];
    const float* w3 = (const float*)d_in[6];
    const float* b3 = (const float*)d_in[7];
    const float* w4 = (const float*)d_in[8];
    const float* b4 = (const float*)d_in[9];
    const float* fcw = (const float*)d_in[10];
    const float* fcb = (const float*)d_in[11];
    float* out = (float*)d_out;

    float *A, *B_, *C;
    cudaGetSymbolAddress((void**)&A,  g_bufA);
    cudaGetSymbolAddress((void**)&B_, g_bufB);
    cudaGetSymbolAddress((void**)&C,  g_bufC);

    // embed: C = X (64, 64, 1024)
    embed_kernel<<<256, 256>>>(tokens, emb, C);

    // layer 0: conv (groups 64, Cin/g 1, NF 10, KS 7), Sin 1024 -> 1030, fold -> 320ch
    conv_fold_kernel<1, 10, 7><<<64 * 32 * 5, 128>>>(C, w1, b1, A, 1024, 1030, 32, 5);
    kmax_tanh_kernel<<<64 * 320, 256>>>(A, B_, 1030, 768);

    // layer 1: groups 32, Cin/g 10, NF 14, KS 5, Sin 768 -> 772, fold -> 224ch
    conv_fold_kernel<10, 14, 5><<<64 * 16 * 4, 128>>>(B_, w2, b2, A, 768, 772, 16, 4);
    kmax_tanh_kernel<<<64 * 224, 256>>>(A, C, 772, 512);

    // layer 2: groups 16, Cin/g 14, NF 18, KS 5, Sin 512 -> 516, fold -> 144ch
    conv_fold_kernel<14, 18, 5><<<64 * 8 * 3, 128>>>(C, w3, b3, A, 512, 516, 8, 3);
    kmax_tanh_kernel<<<64 * 144, 256>>>(A, B_, 516, 256);

    // layer 3: groups 8, Cin/g 18, NF 22, KS 3, Sin 256 -> 258, fold -> 88ch
    conv_fold_kernel<18, 22, 3><<<64 * 4 * 2, 128>>>(B_, w4, b4, A, 256, 258, 4, 2);
    kmax_tanh_kernel<<<64 * 88, 256>>>(A, B_, 258, 4);

    // fc: (64, 352) @ (6, 352)^T + bias -> (64, 6)
    fc_kernel<<<3, 128>>>(B_, fcw, fcb, out);
}

// round 3
// speedup vs baseline: 2.5970x; 2.5970x over previous
#include <cuda_runtime.h>
#include <cuda_bf16.h>
#include <math.h>

// ---------------------------------------------------------------------------
// DeepDCNN: emb-gather -> 4x [grouped conv -> fold -> ordered top-k -> tanh] -> FC
// B=64, SEQ=1024, E=64, NC=6
// Layer i: Ghalf=[32,16,8,4], Cin/group=[1,10,14,18], NF=[10,14,18,22],
//          KS=[7,5,5,3], SOUT=Sin+KS-1, kpool=[768,512,256,4]
// ---------------------------------------------------------------------------

__device__ float g_bufA[21094400]; // max conv-out (layer0: 64*320*1030)
__device__ float g_bufB[15728640]; // max pooled   (layer0: 64*320*768)
__device__ float g_bufC[7340032];  // embed (4.19M) / pooled layer1 (7.34M)

// ---------------------------------------------------------------------------
// 1) Embedding gather + transpose: X[b][e][s] = emb[tokens[b][s]][e]
// ---------------------------------------------------------------------------
__global__ void embed_kernel(const int* __restrict__ tokens,
                             const float* __restrict__ emb,
                             float* __restrict__ X)
{
    int idx = blockIdx.x * 256 + threadIdx.x;   // (b, s) flattened
    int b = idx >> 10;
    int s = idx & 1023;
    int tok = tokens[idx];
    const float* er = emb + (long long)tok * 64;
    float* xr = X + (long long)b * 64 * 1024 + s;
    #pragma unroll 8
    for (int e = 0; e < 64; ++e)
        xr[(long long)e * 1024] = er[e];
}

// ---------------------------------------------------------------------------
// 2) Fused grouped conv + bias + fold. Each thread computes SPT = TS/THREADS
//    s-positions (strided by THREADS) so the NF broadcast weight-LDS amortizes
//    over SPT*NF FMAs.
// ---------------------------------------------------------------------------
template<int CING, int NF, int KS, int THREADS, int TS>
__global__ __launch_bounds__(THREADS)
void conv_fold_kernel(const float* __restrict__ x, const float* __restrict__ w,
                      const float* __restrict__ bias, float* __restrict__ y,
                      int SIN, int SOUT, int Ghalf, int stiles)
{
    constexpr int LX  = TS + KS - 1;
    constexpr int SPT = TS / THREADS;
    __shared__ float sw[2 * NF * CING * KS];
    __shared__ float sx[2 * CING * LX];

    int bid  = blockIdx.x;
    int tile = bid % stiles;
    int gp   = (bid / stiles) % Ghalf;
    int b    = bid / (stiles * Ghalf);
    int t    = threadIdx.x;
    int s0   = tile * TS;

    const int CH_IN  = Ghalf * 2 * CING;
    const int CH_OUT = Ghalf * NF;

    // weights for the paired groups (contiguous slab in global)
    for (int e = t; e < 2 * NF * CING * KS; e += THREADS)
        sw[e] = w[(long long)(2 * gp) * NF * CING * KS + e];
    // input tile + halo, zero-padded
    const float* xb = x + (long long)b * CH_IN * SIN;
    for (int e = t; e < 2 * CING * LX; e += THREADS) {
        int pc = e / LX;
        int i  = e % LX;
        int gs = s0 - (KS - 1) + i;
        float v = 0.f;
        if (gs >= 0 && gs < SIN)
            v = xb[(long long)(2 * gp * CING + pc) * SIN + gs];
        sx[e] = v;
    }
    __syncthreads();

    if (s0 + t < SOUT) {   // threads whose first position is OOB do nothing
        float acc[SPT][NF];
        #pragma unroll
        for (int f = 0; f < NF; ++f) {
            float bb = bias[(2 * gp) * NF + f] + bias[(2 * gp + 1) * NF + f];
            #pragma unroll
            for (int q = 0; q < SPT; ++q) acc[q][f] = bb;
        }

        for (int p = 0; p < 2; ++p) {
            for (int c = 0; c < CING; ++c) {
                const float* sxr = &sx[(p * CING + c) * LX];
                const float* swr = &sw[p * NF * CING * KS + c * KS];
                #pragma unroll
                for (int j = 0; j < KS; ++j) {
                    float xv[SPT];
                    #pragma unroll
                    for (int q = 0; q < SPT; ++q)
                        xv[q] = sxr[t + q * THREADS + j];
                    #pragma unroll
                    for (int f = 0; f < NF; ++f) {
                        float wv = swr[f * CING * KS + j];
                        #pragma unroll
                        for (int q = 0; q < SPT; ++q)
                            acc[q][f] = fmaf(wv, xv[q], acc[q][f]);
                    }
                }
            }
        }

        float* yb = y + (long long)b * CH_OUT * SOUT + (long long)gp * NF * SOUT;
        #pragma unroll
        for (int f = 0; f < NF; ++f) {
            #pragma unroll
            for (int q = 0; q < SPT; ++q) {
                int s = s0 + t + q * THREADS;
                if (s < SOUT) yb[(long long)f * SOUT + s] = acc[q][f];
            }
        }
    }
}

// ---------------------------------------------------------------------------
// 3) Ordered top-k + tanh per row. One 256-thread block per (b, channel) row.
// Radix-select (MSB-first, 8-bit digits) over monotone-flipped keys with
// warp-aggregated histograms and a fully parallel suffix-scan digit select;
// then a stable prefix-sum compaction keeping keys > T plus the first
// need_eq keys == T (lax.top_k tie order), fused with tanh.
// ---------------------------------------------------------------------------
__global__ __launch_bounds__(256)
void kmax_tanh_kernel(const float* __restrict__ x, float* __restrict__ y,
                      int n, int k)
{
    __shared__ unsigned skey[1032];
    __shared__ int hist[256];
    __shared__ int warpsum[8];
    __shared__ unsigned sh_dig, sh_krem, sh_done, sh_tot;

    int row  = blockIdx.x;
    int t    = threadIdx.x;
    int lane = t & 31, wid = t >> 5;
    const float* xr = x + (long long)row * n;

    for (int i = t; i < n; i += 256) {
        unsigned u = __float_as_uint(xr[i]);
        skey[i] = (u & 0x80000000u) ? ~u : (u | 0x80000000u);
    }
    if (t == 0) sh_done = 0;
    __syncthreads();

    unsigned prefix = 0;
    int krem = k;
    int need_eq = 0;

    for (int shift = 24; shift >= 0; shift -= 8) {
        if (sh_done) break;   // block-uniform (shared), safe
        hist[t] = 0;
        __syncthreads();
        unsigned hm = (shift == 24) ? 0u : (0xFFFFFFFFu << (shift + 8));
        for (int base = 0; base < n; base += 256) {
            int i = base + t;
            bool ok = false;
            unsigned key = 0;
            if (i < n) { key = skey[i]; ok = ((key & hm) == prefix); }
            unsigned ball = __ballot_sync(0xFFFFFFFFu, ok);
            if (ok) {
                int d = (int)((key >> shift) & 255u);
                unsigned m = __match_any_sync(ball, d);
                if (lane == (__ffs(m) - 1))
                    atomicAdd(&hist[d], __popc(m));
            }
        }
        __syncthreads();

        // parallel suffix-sum: suf(b) = sum_{bb>=b} hist[bb], b = 255 - t
        int b = 255 - t;
        int h = hist[b];
        int v = h;
        #pragma unroll
        for (int off = 1; off < 32; off <<= 1) {
            int u = __shfl_up_sync(0xFFFFFFFFu, v, off);
            if (lane >= off) v += u;
        }
        if (lane == 31) warpsum[wid] = v;
        __syncthreads();
        if (t < 8) {
            int wv = warpsum[t];
            int vv = wv;
            #pragma unroll
            for (int off = 1; off < 8; off <<= 1) {
                int u = __shfl_up_sync(0xFFu, vv, off);
                if (t >= off) vv += u;
            }
            warpsum[t] = vv - wv;   // exclusive across warps
        }
        __syncthreads();
        int suf = v + warpsum[wid];
        int cum = suf - h;          // count of keys strictly above bucket b
        if (suf >= krem && cum < krem) {   // exactly one thread
            sh_dig  = (unsigned)b;
            sh_krem = (unsigned)(krem - cum);
            // whole bucket kept and low bits remain -> everything >= prefix
            // is kept; no need to refine further digits
            if (h == krem - cum && shift > 0) sh_done = 1;
        }
        __syncthreads();
        prefix |= (sh_dig << shift);
        krem = (int)sh_krem;
        __syncthreads();
    }
    need_eq = sh_done ? 1030 + 8 : krem;   // sh_done: keep every key == T too
    const unsigned T = prefix;
    __syncthreads();

    // stable compaction + tanh
    int carry_gt = 0, carry_eq = 0;
    for (int base = 0; base < n; base += 256) {
        int i = base + t;
        unsigned key = 0;
        int gt = 0, eq = 0;
        if (i < n) { key = skey[i]; gt = key > T; eq = key == T; }
        unsigned pk = ((unsigned)gt << 16) | (unsigned)eq;
        unsigned v2 = pk;
        #pragma unroll
        for (int off = 1; off < 32; off <<= 1) {
            unsigned u = __shfl_up_sync(0xFFFFFFFFu, v2, off);
            if (lane >= off) v2 += u;
        }
        if (lane == 31) warpsum[wid] = (int)v2;
        __syncthreads();
        if (t < 8) {
            unsigned wv = (unsigned)warpsum[t];
            unsigned vv = wv;
            #pragma unroll
            for (int off = 1; off < 8; off <<= 1) {
                unsigned u = __shfl_up_sync(0xFFu, vv, off);
                if (t >= off) vv += u;
            }
            warpsum[t] = (int)(vv - wv);
            if (t == 7) sh_tot = vv;
        }
        __syncthreads();
        unsigned excl = v2 - pk + (unsigned)warpsum[wid];
        int ggt = carry_gt + (int)(excl >> 16);
        int geq = carry_eq + (int)(excl & 0xFFFFu);
        if (i < n && (gt || (eq && geq < need_eq))) {
            int pos = ggt + min(geq, need_eq);
            float f = (key & 0x80000000u) ? __uint_as_float(key & 0x7FFFFFFFu)
                                          : __uint_as_float(~key);
            y[(long long)row * k + pos] = tanhf(f);
        }
        carry_gt += (int)(sh_tot >> 16);
        carry_eq += (int)(sh_tot & 0xFFFFu);
        __syncthreads();
    }
}

// ---------------------------------------------------------------------------
// 4) Final FC: out[b][n] = fcb[n] + sum_i x[b][i] * fcw[n][i],  i < 352
// ---------------------------------------------------------------------------
__global__ void fc_kernel(const float* __restrict__ x, const float* __restrict__ fcw,
                          const float* __restrict__ fcb, float* __restrict__ out)
{
    int t = blockIdx.x * blockDim.x + threadIdx.x;
    if (t >= 64 * 6) return;
    int b = t / 6, n = t % 6;
    const float* xr = x + b * 352;
    const float* wr = fcw + n * 352;
    float acc = fcb[n];
    #pragma unroll 4
    for (int i = 0; i < 352; ++i) acc = fmaf(xr[i], wr[i], acc);
    out[t] = acc;
}

// ---------------------------------------------------------------------------
extern "C" void kernel_launch(void* const* d_in, const int* in_sizes, int n_in,
                              void* d_out, int out_size)
{
    (void)in_sizes; (void)n_in; (void)out_size;
    const int*   tokens = (const int*)  d_in[0];
    const float* emb    = (const float*)d_in[1];
    const float* w1 = (const float*)d_in[2];
    const float* b1 = (const float*)d_in[3];
    const float* w2 = (const float*)d_in[4];
    const float* b2 = (const float*)d_in[5];
    const float* w3 = (const float*)d_in[6];
    const float* b3 = (const float*)d_in[7];
    const float* w4 = (const float*)d_in[8];
    const float* b4 = (const float*)d_in[9];
    const float* fcw = (const float*)d_in[10];
    const float* fcb = (const float*)d_in[11];
    float* out = (float*)d_out;

    float *A, *B_, *C;
    cudaGetSymbolAddress((void**)&A,  g_bufA);
    cudaGetSymbolAddress((void**)&B_, g_bufB);
    cudaGetSymbolAddress((void**)&C,  g_bufC);

    // embed: C = X (64, 64, 1024)
    embed_kernel<<<256, 256>>>(tokens, emb, C);

    // layer 0: Ghalf=32, Sin 1024 -> 1030, kpool 768
    conv_fold_kernel<1, 10, 7, 128, 512><<<64 * 32 * 3, 128>>>(C, w1, b1, A, 1024, 1030, 32, 3);
    kmax_tanh_kernel<<<64 * 320, 256>>>(A, B_, 1030, 768);

    // layer 1: Ghalf=16, Sin 768 -> 772, kpool 512
    conv_fold_kernel<10, 14, 5, 128, 512><<<64 * 16 * 2, 128>>>(B_, w2, b2, A, 768, 772, 16, 2);
    kmax_tanh_kernel<<<64 * 224, 256>>>(A, C, 772, 512);

    // layer 2: Ghalf=8, Sin 512 -> 516, kpool 256
    conv_fold_kernel<14, 18, 5, 64, 256><<<64 * 8 * 3, 64>>>(C, w3, b3, A, 512, 516, 8, 3);
    kmax_tanh_kernel<<<64 * 144, 256>>>(A, B_, 516, 256);

    // layer 3: Ghalf=4, Sin 256 -> 258, kpool 4
    conv_fold_kernel<18, 22, 3, 64, 256><<<64 * 4 * 2, 64>>>(B_, w4, b4, A, 256, 258, 4, 2);
    kmax_tanh_kernel<<<64 * 88, 256>>>(A, B_, 258, 4);

    // fc: (64, 352) @ (6, 352)^T + bias -> (64, 6)
    fc_kernel<<<3, 128>>>(B_, fcw, fcb, out);
}

// round 6
// speedup vs baseline: 3.0004x; 1.1553x over previous
#include <cuda_runtime.h>
#include <cuda_bf16.h>
#include <math.h>

// ---------------------------------------------------------------------------
// DeepDCNN: emb-gather -> 4x [grouped conv -> fold -> ordered top-k -> tanh] -> FC
// B=64, SEQ=1024, E=64, NC=6
// Layer i: Ghalf=[32,16,8,4], Cin/group=[1,10,14,18], NF=[10,14,18,22],
//          KS=[7,5,5,3], SOUT=Sin+KS-1, kpool=[768,512,256,4]
// ---------------------------------------------------------------------------

__device__ float g_bufA[21094400]; // max conv-out (layer0: 64*320*1030)
__device__ float g_bufB[15728640]; // max pooled   (layer0: 64*320*768)
__device__ float g_bufC[7340032];  // embed (4.19M) / pooled layer1 (7.34M)

// ---------------------------------------------------------------------------
// 1) Embedding gather + transpose via smem: X[b][e][s] = emb[tokens[b][s]][e]
// ---------------------------------------------------------------------------
__global__ __launch_bounds__(256)
void embed_kernel(const int* __restrict__ tokens,
                  const float* __restrict__ emb,
                  float* __restrict__ X)
{
    __shared__ float sm[64 * 65];
    __shared__ int stok[64];
    int blk = blockIdx.x;            // B * 16 blocks
    int b   = blk >> 4;
    int s0  = (blk & 15) << 6;
    int t   = threadIdx.x;

    if (t < 64) stok[t] = tokens[b * 1024 + s0 + t];
    __syncthreads();

    // load 64 emb rows (64 floats each) coalesced
    for (int i = t; i < 64 * 16; i += 256) {
        int r  = i >> 4;             // token row
        int c4 = i & 15;             // float4 column
        float4 v = *reinterpret_cast<const float4*>(emb + (long long)stok[r] * 64 + c4 * 4);
        float* d = &sm[r * 65 + c4 * 4];
        d[0] = v.x; d[1] = v.y; d[2] = v.z; d[3] = v.w;
    }
    __syncthreads();

    // write transposed, coalesced over s
    for (int i = t; i < 64 * 64; i += 256) {
        int e = i >> 6, s = i & 63;
        X[((long long)b * 64 + e) * 1024 + s0 + s] = sm[s * 65 + e];
    }
}

// ---------------------------------------------------------------------------
// 2) Fused grouped conv + bias + fold, packed f32x2 FMA.
//    Accumulators packed over feature PAIRS (NF even); weights relaid in smem
//    f-innermost so the packed weight operand is one broadcast LDS.64
//    (smem array force-aligned to 16B — LDS.64 alignment is a HW trap).
//    x windows read directly from global (predicated scalar, L1-cached),
//    duplicated into (x,x) once per window element.
//    Each thread computes 4 consecutive s positions.
// ---------------------------------------------------------------------------
template<int CING, int NF, int KS, int THREADS>
__global__ __launch_bounds__(THREADS)
void conv_fold_kernel(const float* __restrict__ x, const float* __restrict__ w,
                      const float* __restrict__ bias, float* __restrict__ y,
                      int SIN, int SOUT, int Ghalf, int stiles)
{
    constexpr int TS  = THREADS * 4;
    constexpr int NFP = NF / 2;
    constexpr int WIN = KS + 3;          // window floats per (p,c)
    constexpr int WN  = 2 * NF * CING * KS;
    __shared__ __align__(16) float swT[WN];   // layout [p][c][j][f], 16B-aligned
    // even f-pair index -> 8B-aligned LDS.64 (required: misalign traps err715)

    int bid  = blockIdx.x;
    int tile = bid % stiles;
    int gp   = (bid / stiles) % Ghalf;
    int b    = bid / (stiles * Ghalf);
    int t    = threadIdx.x;
    int s0   = tile * TS;

    const int CH_IN  = Ghalf * 2 * CING;
    const int CH_OUT = Ghalf * NF;

    // transpose weights of the paired groups into smem, f innermost
    const float* wg = w + (long long)(2 * gp) * NF * CING * KS;
    for (int e = t; e < WN; e += THREADS) {
        int j  = e % KS;
        int r  = e / KS;
        int c  = r % CING;
        int r2 = r / CING;
        int f  = r2 % NF;
        int p  = r2 / NF;
        swT[((p * CING + c) * KS + j) * NF + f] = wg[e];
    }
    __syncthreads();

    int sbase = s0 + 4 * t;
    if (sbase >= SOUT) return;

    // packed accumulators: acc[fp][q] = (f=2fp, f=2fp+1) at position sbase+q
    unsigned long long acc[NFP][4];
    #pragma unroll
    for (int fp = 0; fp < NFP; ++fp) {
        float blo = bias[2 * gp * NF + 2 * fp]     + bias[(2 * gp + 1) * NF + 2 * fp];
        float bhi = bias[2 * gp * NF + 2 * fp + 1] + bias[(2 * gp + 1) * NF + 2 * fp + 1];
        unsigned long long pb;
        asm("mov.b64 %0, {%1, %2};" : "=l"(pb)
            : "r"(__float_as_uint(blo)), "r"(__float_as_uint(bhi)));
        #pragma unroll
        for (int q = 0; q < 4; ++q) acc[fp][q] = pb;
    }

    const float* xb = x + (long long)b * CH_IN * SIN + (long long)(2 * gp * CING) * SIN;
    int gbase = sbase - (KS - 1);

    #pragma unroll 1
    for (int pc = 0; pc < 2 * CING; ++pc) {
        const float* xr = xb + (long long)pc * SIN;
        // window, duplicated into both f32x2 halves
        unsigned long long xd[WIN];
        #pragma unroll
        for (int i = 0; i < WIN; ++i) {
            int g = gbase + i;
            float v = ((unsigned)g < (unsigned)SIN) ? __ldg(&xr[g]) : 0.f;
            asm("mov.b64 %0, {%1, %1};" : "=l"(xd[i]) : "r"(__float_as_uint(v)));
        }
        const float* wrow = &swT[pc * KS * NF];
        #pragma unroll
        for (int j = 0; j < KS; ++j) {
            #pragma unroll
            for (int fp = 0; fp < NFP; ++fp) {
                unsigned long long wp =
                    *reinterpret_cast<const unsigned long long*>(&wrow[j * NF + 2 * fp]);
                #pragma unroll
                for (int q = 0; q < 4; ++q)
                    asm("fma.rn.f32x2 %0, %1, %2, %0;"
                        : "+l"(acc[fp][q]) : "l"(xd[j + q]), "l"(wp));
            }
        }
    }

    float* yb = y + (long long)b * CH_OUT * SOUT + (long long)gp * NF * SOUT;
    #pragma unroll
    for (int fp = 0; fp < NFP; ++fp) {
        #pragma unroll
        for (int q = 0; q < 4; ++q) {
            int s = sbase + q;
            if (s < SOUT) {
                unsigned lo, hi;
                asm("mov.b64 {%0, %1}, %2;" : "=r"(lo), "=r"(hi) : "l"(acc[fp][q]));
                yb[(long long)(2 * fp)     * SOUT + s] = __uint_as_float(lo);
                yb[(long long)(2 * fp + 1) * SOUT + s] = __uint_as_float(hi);
            }
        }
    }
}

// ---------------------------------------------------------------------------
// 3) Ordered top-k + tanh per row. One 256-thread block per (b, channel) row.
// Radix-select (MSB-first, 8-bit digits) with warp-aggregated histograms,
// parallel suffix-scan digit select, then stable compaction + tanh.
// (unchanged from passing R3 kernel)
// ---------------------------------------------------------------------------
__global__ __launch_bounds__(256)
void kmax_tanh_kernel(const float* __restrict__ x, float* __restrict__ y,
                      int n, int k)
{
    __shared__ unsigned skey[1032];
    __shared__ int hist[256];
    __shared__ int warpsum[8];
    __shared__ unsigned sh_dig, sh_krem, sh_done, sh_tot;

    int row  = blockIdx.x;
    int t    = threadIdx.x;
    int lane = t & 31, wid = t >> 5;
    const float* xr = x + (long long)row * n;

    for (int i = t; i < n; i += 256) {
        unsigned u = __float_as_uint(xr[i]);
        skey[i] = (u & 0x80000000u) ? ~u : (u | 0x80000000u);
    }
    if (t == 0) sh_done = 0;
    __syncthreads();

    unsigned prefix = 0;
    int krem = k;
    int need_eq = 0;

    for (int shift = 24; shift >= 0; shift -= 8) {
        if (sh_done) break;   // block-uniform (shared), safe
        hist[t] = 0;
        __syncthreads();
        unsigned hm = (shift == 24) ? 0u : (0xFFFFFFFFu << (shift + 8));
        for (int base = 0; base < n; base += 256) {
            int i = base + t;
            bool ok = false;
            unsigned key = 0;
            if (i < n) { key = skey[i]; ok = ((key & hm) == prefix); }
            unsigned ball = __ballot_sync(0xFFFFFFFFu, ok);
            if (ok) {
                int d = (int)((key >> shift) & 255u);
                unsigned m = __match_any_sync(ball, d);
                if (lane == (__ffs(m) - 1))
                    atomicAdd(&hist[d], __popc(m));
            }
        }
        __syncthreads();

        // parallel suffix-sum: suf(b) = sum_{bb>=b} hist[bb], b = 255 - t
        int b = 255 - t;
        int h = hist[b];
        int v = h;
        #pragma unroll
        for (int off = 1; off < 32; off <<= 1) {
            int u = __shfl_up_sync(0xFFFFFFFFu, v, off);
            if (lane >= off) v += u;
        }
        if (lane == 31) warpsum[wid] = v;
        __syncthreads();
        if (t < 8) {
            int wv = warpsum[t];
            int vv = wv;
            #pragma unroll
            for (int off = 1; off < 8; off <<= 1) {
                int u = __shfl_up_sync(0xFFu, vv, off);
                if (t >= off) vv += u;
            }
            warpsum[t] = vv - wv;   // exclusive across warps
        }
        __syncthreads();
        int suf = v + warpsum[wid];
        int cum = suf - h;          // count of keys strictly above bucket b
        if (suf >= krem && cum < krem) {   // exactly one thread
            sh_dig  = (unsigned)b;
            sh_krem = (unsigned)(krem - cum);
            if (h == krem - cum && shift > 0) sh_done = 1;
        }
        __syncthreads();
        prefix |= (sh_dig << shift);
        krem = (int)sh_krem;
        __syncthreads();
    }
    need_eq = sh_done ? 1030 + 8 : krem;   // sh_done: keep every key == T too
    const unsigned T = prefix;
    __syncthreads();

    // stable compaction + tanh
    int carry_gt = 0, carry_eq = 0;
    for (int base = 0; base < n; base += 256) {
        int i = base + t;
        unsigned key = 0;
        int gt = 0, eq = 0;
        if (i < n) { key = skey[i]; gt = key > T; eq = key == T; }
        unsigned pk = ((unsigned)gt << 16) | (unsigned)eq;
        unsigned v2 = pk;
        #pragma unroll
        for (int off = 1; off < 32; off <<= 1) {
            unsigned u = __shfl_up_sync(0xFFFFFFFFu, v2, off);
            if (lane >= off) v2 += u;
        }
        if (lane == 31) warpsum[wid] = (int)v2;
        __syncthreads();
        if (t < 8) {
            unsigned wv = (unsigned)warpsum[t];
            unsigned vv = wv;
            #pragma unroll
            for (int off = 1; off < 8; off <<= 1) {
                unsigned u = __shfl_up_sync(0xFFu, vv, off);
                if (t >= off) vv += u;
            }
            warpsum[t] = (int)(vv - wv);
            if (t == 7) sh_tot = vv;
        }
        __syncthreads();
        unsigned excl = v2 - pk + (unsigned)warpsum[wid];
        int ggt = carry_gt + (int)(excl >> 16);
        int geq = carry_eq + (int)(excl & 0xFFFFu);
        if (i < n && (gt || (eq && geq < need_eq))) {
            int pos = ggt + min(geq, need_eq);
            float f = (key & 0x80000000u) ? __uint_as_float(key & 0x7FFFFFFFu)
                                          : __uint_as_float(~key);
            y[(long long)row * k + pos] = tanhf(f);
        }
        carry_gt += (int)(sh_tot >> 16);
        carry_eq += (int)(sh_tot & 0xFFFFu);
        __syncthreads();
    }
}

// ---------------------------------------------------------------------------
// 4) Final FC: out[b][n] = fcb[n] + sum_i x[b][i] * fcw[n][i],  i < 352
// ---------------------------------------------------------------------------
__global__ void fc_kernel(const float* __restrict__ x, const float* __restrict__ fcw,
                          const float* __restrict__ fcb, float* __restrict__ out)
{
    int t = blockIdx.x * blockDim.x + threadIdx.x;
    if (t >= 64 * 6) return;
    int b = t / 6, n = t % 6;
    const float* xr = x + b * 352;
    const float* wr = fcw + n * 352;
    float acc = fcb[n];
    #pragma unroll 4
    for (int i = 0; i < 352; ++i) acc = fmaf(xr[i], wr[i], acc);
    out[t] = acc;
}

// ---------------------------------------------------------------------------
extern "C" void kernel_launch(void* const* d_in, const int* in_sizes, int n_in,
                              void* d_out, int out_size)
{
    (void)in_sizes; (void)n_in; (void)out_size;
    const int*   tokens = (const int*)  d_in[0];
    const float* emb    = (const float*)d_in[1];
    const float* w1 = (const float*)d_in[2];
    const float* b1 = (const float*)d_in[3];
    const float* w2 = (const float*)d_in[4];
    const float* b2 = (const float*)d_in[5];
    const float* w3 = (const float*)d_in[6];
    const float* b3 = (const float*)d_in[7];
    const float* w4 = (const float*)d_in[8];
    const float* b4 = (const float*)d_in[9];
    const float* fcw = (const float*)d_in[10];
    const float* fcb = (const float*)d_in[11];
    float* out = (float*)d_out;

    float *A, *B_, *C;
    cudaGetSymbolAddress((void**)&A,  g_bufA);
    cudaGetSymbolAddress((void**)&B_, g_bufB);
    cudaGetSymbolAddress((void**)&C,  g_bufC);

    // embed: C = X (64, 64, 1024)
    embed_kernel<<<64 * 16, 256>>>(tokens, emb, C);

    // layer 0: Ghalf=32, Sin 1024 -> 1030, kpool 768  (TS=512, stiles=3)
    conv_fold_kernel<1, 10, 7, 128><<<64 * 32 * 3, 128>>>(C, w1, b1, A, 1024, 1030, 32, 3);
    kmax_tanh_kernel<<<64 * 320, 256>>>(A, B_, 1030, 768);

    // layer 1: Ghalf=16, Sin 768 -> 772, kpool 512   (TS=512, stiles=2)
    conv_fold_kernel<10, 14, 5, 128><<<64 * 16 * 2, 128>>>(B_, w2, b2, A, 768, 772, 16, 2);
    kmax_tanh_kernel<<<64 * 224, 256>>>(A, C, 772, 512);

    // layer 2: Ghalf=8, Sin 512 -> 516, kpool 256    (TS=256, stiles=3)
    conv_fold_kernel<14, 18, 5, 64><<<64 * 8 * 3, 64>>>(C, w3, b3, A, 512, 516, 8, 3);
    kmax_tanh_kernel<<<64 * 144, 256>>>(A, B_, 516, 256);

    // layer 3: Ghalf=4, Sin 256 -> 258, kpool 4      (TS=256, stiles=2)
    conv_fold_kernel<18, 22, 3, 64><<<64 * 4 * 2, 64>>>(B_, w4, b4, A, 256, 258, 4, 2);
    kmax_tanh_kernel<<<64 * 88, 256>>>(A, B_, 258, 4);

    // fc: (64, 352) @ (6, 352)^T + bias -> (64, 6)
    fc_kernel<<<3, 128>>>(B_, fcw, fcb, out);
}